// round 16
// baseline (speedup 1.0000x reference)
#include <cuda_runtime.h>
#include <cuda_fp16.h>
#include <cstdint>
#include <cstddef>

#define RB    32
#define NTHR  384
#define KT1   14
#define KT2   24

__device__ uint4 d_W1p[12 * KT1 * 4 * 32];
__device__ uint4 d_W2p[12 * KT2 * 4 * 32];
__device__ uint4 d_WlatP[12 * 2 * 32];
__device__ uint4 d_hs1f[128 * 60 * 768];

struct Smem {
    uint4 frag[2][KT2 * 2 * 32];
    float h2[2][RB * 192];
    float latp[2][12 * 128];
    float sn[RB * 24];
    float bias[768];            // i/f/o pre-scaled by 0.5
    float xinv[900];
    float xmean[900];
    float blat[16];
    float Wout[80];
    float bout[5];
    float Wsfco[5 * 193];
    float bsfco[5];
    float ysca[5];
    float yslev[300];
};

__device__ __forceinline__ float tanhf_fast(float x) {
    float y; asm("tanh.approx.f32 %0, %1;" : "=f"(y) : "f"(x)); return y;
}
__device__ __forceinline__ __half2 tanh_h2(__half2 x) {
    __half2 y;
    asm("tanh.approx.f16x2 %0, %1;" : "=r"(*(uint32_t*)&y) : "r"(*(uint32_t*)&x));
    return y;
}
__device__ __forceinline__ uint32_t h2pack(float x, float y) {
    __half2 h = __floats2half2_rn(x, y);
    return *reinterpret_cast<uint32_t*>(&h);
}

__device__ __forceinline__ void put_frag(uint32_t* fw, int row, int p, float v0, float v1) {
    int kt = p >> 3, qq = p & 7, mt = row >> 4, rr = row & 15;
    int cell = (kt * 2 + mt) * 32 + (rr & 7) * 4 + (qq & 3);
    int reg  = (qq >> 2) * 2 + (rr >> 3);
    fw[cell * 4 + reg] = h2pack(v0, v1);
}

__device__ __forceinline__ void mma4(float* c, const uint32_t* a, uint32_t b0, uint32_t b1) {
    asm volatile(
        "mma.sync.aligned.m16n8k16.row.col.f32.f16.f16.f32 "
        "{%0,%1,%2,%3},{%4,%5,%6,%7},{%8,%9},{%0,%1,%2,%3};\n"
        : "+f"(c[0]), "+f"(c[1]), "+f"(c[2]), "+f"(c[3])
        : "r"(a[0]), "r"(a[1]), "r"(a[2]), "r"(a[3]), "r"(b0), "r"(b1));
}

__device__ __forceinline__ void cpa16(uint32_t dst, const void* src) {
    asm volatile("cp.async.cg.shared.global [%0], [%1], 16;" :: "r"(dst), "l"(src) : "memory");
}

__device__ __forceinline__ void gemm_pro(
    const uint4* __restrict__ wsrc, const float* __restrict__ sbias,
    int cg, int lane, float acc[2][8][4], uint4 (&wv)[3][4])
{
    int l2i = lane & 3;
#pragma unroll
    for (int nt = 0; nt < 8; nt++) {
        float b0 = sbias[(nt >> 1) * 192 + cg * 16 + (nt & 1) * 8 + 2 * l2i];
        float b1 = sbias[(nt >> 1) * 192 + cg * 16 + (nt & 1) * 8 + 2 * l2i + 1];
        acc[0][nt][0] = b0; acc[0][nt][1] = b1; acc[0][nt][2] = b0; acc[0][nt][3] = b1;
        acc[1][nt][0] = b0; acc[1][nt][1] = b1; acc[1][nt][2] = b0; acc[1][nt][3] = b1;
    }
    const uint4* wp = wsrc + lane;
#pragma unroll
    for (int np = 0; np < 4; np++) wv[0][np] = __ldg(&wp[np * 32]);
#pragma unroll
    for (int np = 0; np < 4; np++) wv[1][np] = __ldg(&wp[(4 + np) * 32]);
}

template<int KT>
__device__ __forceinline__ void gemm_main(
    const uint4* __restrict__ fr, const uint4* __restrict__ wsrc,
    int lane, float acc[2][8][4], uint4 (&wv)[3][4])
{
    const uint4* wp = wsrc + lane;
    const uint4* fb = fr + lane;
    uint4 f[2][2];
    f[0][0] = fb[0]; f[0][1] = fb[32];
#pragma unroll
    for (int kt = 0; kt < KT; kt++) {
        const int cur = kt % 3;
        if (kt + 2 < KT) {
            const uint4* wpn = wp + (kt + 2) * 4 * 32;
            const int nb = (kt + 2) % 3;
#pragma unroll
            for (int np = 0; np < 4; np++) wv[nb][np] = __ldg(&wpn[np * 32]);
        }
        if (kt + 1 < KT) {
            f[(kt + 1) & 1][0] = fb[(kt + 1) * 64];
            f[(kt + 1) & 1][1] = fb[(kt + 1) * 64 + 32];
        }
        const uint32_t* a0 = (const uint32_t*)&f[kt & 1][0];
        const uint32_t* a1 = (const uint32_t*)&f[kt & 1][1];
#pragma unroll
        for (int np = 0; np < 4; np++) {
            mma4(acc[0][2 * np],     a0, wv[cur][np].x, wv[cur][np].y);
            mma4(acc[1][2 * np],     a1, wv[cur][np].x, wv[cur][np].y);
            mma4(acc[0][2 * np + 1], a0, wv[cur][np].z, wv[cur][np].w);
            mma4(acc[1][2 * np + 1], a1, wv[cur][np].z, wv[cur][np].w);
        }
    }
#pragma unroll
    for (int np = 0; np < 8; np++)
        asm volatile("prefetch.global.L1 [%0];" :: "l"((const void*)(wp + np * 32)));
}

// gates i/f/g fp32 (precision-critical); output stage f16x2
__device__ __forceinline__ uint32_t ew_pair(const float acc[8][4], float* cr,
                                            int j, int q) {
    float gi0 = acc[0+j][2*q], gi1 = acc[0+j][2*q+1];
    float gf0 = acc[2+j][2*q], gf1 = acc[2+j][2*q+1];
    float gg0 = acc[4+j][2*q], gg1 = acc[4+j][2*q+1];
    float go0 = acc[6+j][2*q], go1 = acc[6+j][2*q+1];
    float si0 = fmaf(tanhf_fast(gi0), 0.5f, 0.5f);
    float si1 = fmaf(tanhf_fast(gi1), 0.5f, 0.5f);
    float sf0 = fmaf(tanhf_fast(gf0), 0.5f, 0.5f);
    float sf1 = fmaf(tanhf_fast(gf1), 0.5f, 0.5f);
    float c0 = sf0 * cr[0] + si0 * tanhf_fast(gg0);
    float c1 = sf1 * cr[1] + si1 * tanhf_fast(gg1);
    cr[0] = c0; cr[1] = c1;
    const __half2 hh = __floats2half2_rn(0.5f, 0.5f);
    __half2 so = __hfma2(tanh_h2(__floats2half2_rn(go0, go1)), hh, hh);
    __half2 h = __hmul2(so, tanh_h2(__floats2half2_rn(c0, c1)));
    return *reinterpret_cast<uint32_t*>(&h);
}

__device__ __forceinline__ void lat_mma(const uint4* __restrict__ fr, float* __restrict__ latp,
                                        int w, int lane) {
    int mt = w / 6, rem = w % 6, ntL = rem / 3, ktr = rem % 3;
    float acc[4] = {0.f, 0.f, 0.f, 0.f};
    const uint4* fb = fr + mt * 32 + lane;
#pragma unroll
    for (int i = 0; i < 4; i++) {
        int kt = ktr * 4 + i;
        uint4 f = fb[kt * 64];
        uint4 u = __ldg(&d_WlatP[(kt * 2 + ntL) * 32 + lane]);
        mma4(acc, (const uint32_t*)&f, u.x, u.y);
        mma4(acc, (const uint32_t*)&f, u.z, u.w);
    }
    float* base = latp + w * 128;
    int r0 = lane >> 2, c0 = (lane & 3) * 2;
    *(float2*)&base[r0 * 8 + c0]       = make_float2(acc[0], acc[1]);
    *(float2*)&base[(r0 + 8) * 8 + c0] = make_float2(acc[2], acc[3]);
}

__device__ __forceinline__ void lat_reduce(Smem& s, const float* __restrict__ lp,
    int lm, int bbase, int tid, float* __restrict__ out_lat, float* __restrict__ out_lev)
{
#pragma unroll 1
    for (int it = 0; it < 2; it++) {
        int idx = it * NTHR + tid;
        if (idx < 512) {
            int r = idx >> 4, j16 = idx & 15;
            int mt = r >> 4, rr = r & 15, ntL = j16 >> 3, cc = j16 & 7;
            int tb = mt * 6 + ntL * 3;
            float sum = s.blat[j16]
                      + lp[(tb + 0) * 128 + rr * 8 + cc]
                      + lp[(tb + 1) * 128 + rr * 8 + cc]
                      + lp[(tb + 2) * 128 + rr * 8 + cc];
            out_lat[((size_t)(bbase + r) * 60 + lm) * 16 + j16] = sum;
            float v0 = sum * s.Wout[0 * 16 + j16];
            float v1 = sum * s.Wout[1 * 16 + j16];
            float v2 = sum * s.Wout[2 * 16 + j16];
            float v3 = sum * s.Wout[3 * 16 + j16];
            float v4 = sum * s.Wout[4 * 16 + j16];
#pragma unroll
            for (int off = 8; off >= 1; off >>= 1) {
                v0 += __shfl_xor_sync(0xffffffffu, v0, off, 16);
                v1 += __shfl_xor_sync(0xffffffffu, v1, off, 16);
                v2 += __shfl_xor_sync(0xffffffffu, v2, off, 16);
                v3 += __shfl_xor_sync(0xffffffffu, v3, off, 16);
                v4 += __shfl_xor_sync(0xffffffffu, v4, off, 16);
            }
            if (j16 == 0) {
                size_t ob = ((size_t)(bbase + r) * 60 + lm) * 5;
                out_lev[ob + 0] = (v0 + s.bout[0]) * s.yslev[lm * 5 + 0];
                out_lev[ob + 1] = (v1 + s.bout[1]) * s.yslev[lm * 5 + 1];
                out_lev[ob + 2] = (v2 + s.bout[2]) * s.yslev[lm * 5 + 2];
                out_lev[ob + 3] = (v3 + s.bout[3]) * s.yslev[lm * 5 + 3];
                out_lev[ob + 4] = (v4 + s.bout[4]) * s.yslev[lm * 5 + 4];
            }
        }
    }
}

__global__ void pack_kernel(const float* __restrict__ Wih1, const float* __restrict__ Whh1,
                            const float* __restrict__ Wih2, const float* __restrict__ Whh2,
                            const float* __restrict__ Wlat) {
    int tid = blockIdx.x * blockDim.x + threadIdx.x;
    const int N2 = 12 * KT2 * 4 * 32, N1 = 12 * KT1 * 4 * 32, NL = 12 * 2 * 32;
    if (tid < N2) {
        int lane = tid & 31, t = tid >> 5;
        int np = t % 4, kt = (t / 4) % KT2, cg = t / (4 * KT2);
        int k0 = kt * 16 + (lane & 3) * 2;
        int ks[4] = {k0, k0 + 1, k0 + 8, k0 + 9};
        uint32_t word[2][2];
#pragma unroll
        for (int sub = 0; sub < 2; sub++) {
            int c = (np * 2 + sub) * 8 + (lane >> 2);
            int gate = c >> 4;
            float sc = (gate == 2) ? 1.0f : 0.5f;
            int n = gate * 192 + cg * 16 + (c & 15);
            float v[4];
#pragma unroll
            for (int i = 0; i < 4; i++) {
                int k = ks[i];
                v[i] = sc * ((k < 192) ? Whh2[n * 192 + k] : Wih2[n * 192 + (k - 192)]);
            }
            word[sub][0] = h2pack(v[0], v[1]); word[sub][1] = h2pack(v[2], v[3]);
        }
        d_W2p[tid] = make_uint4(word[0][0], word[0][1], word[1][0], word[1][1]);
    } else if (tid < N2 + N1) {
        int t0 = tid - N2;
        int lane = t0 & 31, t = t0 >> 5;
        int np = t % 4, kt = (t / 4) % KT1, cg = t / (4 * KT1);
        int k0 = kt * 16 + (lane & 3) * 2;
        int ks[4] = {k0, k0 + 1, k0 + 8, k0 + 9};
        uint32_t word[2][2];
#pragma unroll
        for (int sub = 0; sub < 2; sub++) {
            int c = (np * 2 + sub) * 8 + (lane >> 2);
            int gate = c >> 4;
            float sc = (gate == 2) ? 1.0f : 0.5f;
            int n = gate * 192 + cg * 16 + (c & 15);
            float v[4];
#pragma unroll
            for (int i = 0; i < 4; i++) {
                int k = ks[i];
                float w;
                if (k < 192)      w = Whh1[n * 192 + k];
                else if (k < 223) w = Wih1[n * 31 + (k - 192)];
                else              w = 0.0f;
                v[i] = sc * w;
            }
            word[sub][0] = h2pack(v[0], v[1]); word[sub][1] = h2pack(v[2], v[3]);
        }
        d_W1p[t0] = make_uint4(word[0][0], word[0][1], word[1][0], word[1][1]);
    } else if (tid < N2 + N1 + NL) {
        int t0 = tid - N2 - N1;
        int lane = t0 & 31, t = t0 >> 5;
        int nt = t % 2, kt = t / 2;
        int n = nt * 8 + (lane >> 2);
        int k0 = kt * 16 + (lane & 3) * 2;
        int ks[4] = {k0, k0 + 1, k0 + 8, k0 + 9};
        float hi[4], lo[4];
#pragma unroll
        for (int i = 0; i < 4; i++) {
            float w = Wlat[n * 192 + ks[i]];
            __half h = __float2half(w);
            hi[i] = __half2float(h);
            lo[i] = w - hi[i];
        }
        d_WlatP[t0] = make_uint4(h2pack(hi[0], hi[1]), h2pack(hi[2], hi[3]),
                                 h2pack(lo[0], lo[1]), h2pack(lo[2], lo[3]));
    }
}

__global__ void __launch_bounds__(NTHR, 1) lstm_main(
    const float* __restrict__ x_lev, const float* __restrict__ x_sfc,
    const float* __restrict__ h_mem,
    const float* __restrict__ xmean_lev, const float* __restrict__ xdiv_lev,
    const float* __restrict__ xmean_sca, const float* __restrict__ xdiv_sca,
    const float* __restrict__ yscale_lev, const float* __restrict__ yscale_sca,
    const float* __restrict__ b1, const float* __restrict__ b2,
    const float* __restrict__ Wsfc1, const float* __restrict__ bsfc1,
    const float* __restrict__ Wsfc2, const float* __restrict__ bsfc2,
    const float* __restrict__ Wtoa1, const float* __restrict__ btoa1,
    const float* __restrict__ Wtoa2, const float* __restrict__ btoa2,
    const float* __restrict__ blat, const float* __restrict__ Wout,
    const float* __restrict__ bout,
    const float* __restrict__ Wsfcout, const float* __restrict__ bsfcout,
    float* __restrict__ out)
{
    extern __shared__ char smraw[];
    Smem& s = *reinterpret_cast<Smem*>(smraw);
    const int tid = threadIdx.x, warp = tid >> 5, lane = tid & 31;
    const int cg = warp;
    const int l2i = lane & 3, l4 = lane >> 2;
    const int bbase = blockIdx.x * RB;
    float* out_lev = out;
    float* out_sfc = out + 4096 * 60 * 5;
    float* out_lat = out_sfc + 4096 * 5;

    for (int i = tid; i < RB * 24; i += NTHR) {
        int r = i / 24, k = i % 24;
        s.sn[i] = (x_sfc[(bbase + r) * 24 + k] - xmean_sca[k]) / xdiv_sca[k];
    }
    for (int i = tid; i < 768; i += NTHR)
        s.bias[i] = ((i / 192) == 2) ? b1[i] : 0.5f * b1[i];
    for (int i = tid; i < 900; i += NTHR) { s.xinv[i] = __frcp_rn(xdiv_lev[i]); s.xmean[i] = xmean_lev[i]; }
    for (int i = tid; i < 16; i += NTHR) s.blat[i] = blat[i];
    for (int i = tid; i < 80; i += NTHR) s.Wout[i] = Wout[i];
    for (int i = tid; i < 5; i += NTHR) {
        s.bout[i] = bout[i]; s.bsfco[i] = bsfcout[i];
        s.ysca[i] = __frcp_rn(yscale_sca[i]);
    }
    for (int i = tid; i < 5 * 192; i += NTHR) { int n = i / 192, k = i % 192; s.Wsfco[n * 193 + k] = Wsfcout[i]; }
    for (int i = tid; i < 300; i += NTHR) s.yslev[i] = __frcp_rn(yscale_lev[i]);
    __syncthreads();

#pragma unroll 1
    for (int it = 0; it < 16; it++) {
        int idx = it * NTHR + tid, r = idx / 192, k = idx % 192;
        float s1 = bsfc1[k], s2 = bsfc2[k];
#pragma unroll 4
        for (int t = 0; t < 24; t++) {
            float v = s.sn[r * 24 + t];
            s1 += v * Wsfc1[k * 24 + t];
            s2 += v * Wsfc2[k * 24 + t];
        }
        s.h2[0][r * 192 + k] = tanhf_fast(s1);
        s.h2[1][r * 192 + k] = tanhf_fast(s2);
    }
    __syncthreads();

    float creg[2][2][2][2];
#pragma unroll
    for (int m = 0; m < 2; m++)
#pragma unroll
        for (int j = 0; j < 2; j++)
#pragma unroll
            for (int q = 0; q < 2; q++)
#pragma unroll
                for (int e = 0; e < 2; e++)
                    creg[m][j][q][e] = s.h2[1][(m * 16 + l4 + 8 * q) * 192 + cg * 16 + 8 * j + 2 * l2i + e];

    int buf = 0;
    for (int it = 0; it < 8; it++) {
        int idx = it * NTHR + tid, r = idx / 96, cp = idx % 96;
        put_frag((uint32_t*)s.frag[0], r, cp, s.h2[0][r * 192 + 2 * cp], s.h2[0][r * 192 + 2 * cp + 1]);
    }
#pragma unroll 1
    for (int it = 0; it < 2; it++) {
        const int ln = 59;
        int idx = it * NTHR + tid;
        if (idx < 512) {
            int r = idx >> 4, p = idx & 15;
            float v[2];
#pragma unroll
            for (int u = 0; u < 2; u++) {
                int j = p * 2 + u;
                int base = (bbase + r) * 60 + ln;
                float val;
                if (j < 15)      val = (x_lev[base * 15 + j] - s.xmean[ln * 15 + j]) * s.xinv[ln * 15 + j];
                else if (j < 31) val = h_mem[base * 16 + (j - 15)];
                else             val = 0.0f;
                v[u] = val;
            }
            put_frag((uint32_t*)s.frag[0], r, 96 + p, v[0], v[1]);
        }
    }

    const uint4* w1src = d_W1p + cg * (KT1 * 4 * 32);
    const uint4* w2src = d_W2p + cg * (KT2 * 4 * 32);
    float acc[2][8][4];
    uint4 wv[3][4];

    gemm_pro(w1src, s.bias, cg, lane, acc, wv);
    __syncthreads();

    // ---- layer 1 ----
    for (int l = 59; l >= 0; l--) {
        gemm_main<KT1>(s.frag[buf], w1src, lane, acc, wv);
        uint32_t* fwN = (uint32_t*)s.frag[buf ^ 1];
        float raw[2][2];
        if (l > 0) {
            const int ln = l - 1;
#pragma unroll 1
            for (int it = 0; it < 2; it++) {
                int idx = it * NTHR + tid;
                if (idx < 512) {
                    int r = idx >> 4, p = idx & 15;
#pragma unroll
                    for (int u = 0; u < 2; u++) {
                        int j = p * 2 + u;
                        int base = (bbase + r) * 60 + ln;
                        if (j < 15)      raw[it][u] = x_lev[base * 15 + j];
                        else if (j < 31) raw[it][u] = h_mem[base * 16 + (j - 15)];
                        else             raw[it][u] = 0.0f;
                    }
                }
            }
        }
#pragma unroll
        for (int m = 0; m < 2; m++) {
            uint32_t wds[4];
#pragma unroll
            for (int j = 0; j < 2; j++)
#pragma unroll
                for (int q = 0; q < 2; q++)
                    wds[2 * j + q] = ew_pair(acc[m], creg[m][j][q], j, q);
            uint4 w4 = make_uint4(wds[0], wds[1], wds[2], wds[3]);
            ((uint4*)fwN)[(cg * 2 + m) * 32 + lane] = w4;
            d_hs1f[(size_t)(blockIdx.x * 60 + l) * 768 + (cg * 2 + m) * 32 + lane] = w4;
        }
        if (l > 0) {
            const int ln = l - 1;
#pragma unroll 1
            for (int it = 0; it < 2; it++) {
                int idx = it * NTHR + tid;
                if (idx < 512) {
                    int r = idx >> 4, p = idx & 15;
                    float v[2];
#pragma unroll
                    for (int u = 0; u < 2; u++) {
                        int j = p * 2 + u;
                        v[u] = (j < 15) ? (raw[it][u] - s.xmean[ln * 15 + j]) * s.xinv[ln * 15 + j]
                                        : raw[it][u];
                    }
                    put_frag(fwN, r, 96 + p, v[0], v[1]);
                }
            }
            gemm_pro(w1src, s.bias, cg, lane, acc, wv);
        }
        __syncthreads();
        buf ^= 1;
    }

    // ---- transition ----  (buf == 0)
    for (int i = tid; i < 768; i += NTHR)
        s.bias[i] = ((i / 192) == 2) ? b2[i] : 0.5f * b2[i];
#pragma unroll 1
    for (int it = 0; it < 16; it++) {
        int idx = it * NTHR + tid, r = idx / 192, k = idx % 192;
        float t0 = s.sn[r * 24 + 0], t1 = s.sn[r * 24 + 1];
        s.h2[0][r * 192 + k] = tanhf_fast(btoa1[k] + t0 * Wtoa1[k * 2] + t1 * Wtoa1[k * 2 + 1]);
        s.h2[1][r * 192 + k] = tanhf_fast(btoa2[k] + t0 * Wtoa2[k * 2] + t1 * Wtoa2[k * 2 + 1]);
    }
    __syncthreads();
#pragma unroll
    for (int m = 0; m < 2; m++)
#pragma unroll
        for (int j = 0; j < 2; j++)
#pragma unroll
            for (int q = 0; q < 2; q++)
#pragma unroll
                for (int e = 0; e < 2; e++)
                    creg[m][j][q][e] = s.h2[1][(m * 16 + l4 + 8 * q) * 192 + cg * 16 + 8 * j + 2 * l2i + e];
    for (int it = 0; it < 8; it++) {
        int idx = it * NTHR + tid, r = idx / 96, cp = idx % 96;
        put_frag((uint32_t*)s.frag[buf], r, cp, s.h2[0][r * 192 + 2 * cp], s.h2[0][r * 192 + 2 * cp + 1]);
    }
    {
        const uint4* src = d_hs1f + (size_t)(blockIdx.x * 60 + 0) * 768;
        uint4* dst = s.frag[buf] + 768;
        dst[tid] = src[tid];
        dst[NTHR + tid] = src[NTHR + tid];
    }
    gemm_pro(w2src, s.bias, cg, lane, acc, wv);
    __syncthreads();

    // ---- layer 2 (lat_reduce deferred one step past the barrier) ----
    for (int l = 0; l < 60; l++) {
        gemm_main<KT2>(s.frag[buf], w2src, lane, acc, wv);
        // deferred reduce of level l-2 (partials latp[(l-1)&1], synced by last barrier)
        if (l >= 2) lat_reduce(s, s.latp[(l - 1) & 1], l - 2, bbase, tid, out_lat, out_lev);
        uint32_t* fwN = (uint32_t*)s.frag[buf ^ 1];
        if (l < 59) {   // start hs1 L2 fetch earliest in the phase
            const uint4* src = d_hs1f + (size_t)(blockIdx.x * 60 + (l + 1)) * 768;
            uint32_t ds = (uint32_t)__cvta_generic_to_shared(s.frag[buf ^ 1] + 768 + tid);
            cpa16(ds, src + tid);
            cpa16(ds + NTHR * 16, src + NTHR + tid);
            asm volatile("cp.async.commit_group;" ::: "memory");
        }
        if (l > 0) lat_mma(s.frag[buf], s.latp[l & 1], warp, lane);
#pragma unroll
        for (int m = 0; m < 2; m++) {
            uint32_t wds[4];
#pragma unroll
            for (int j = 0; j < 2; j++)
#pragma unroll
                for (int q = 0; q < 2; q++) {
                    uint32_t w = ew_pair(acc[m], creg[m][j][q], j, q);
                    wds[2 * j + q] = w;
                    if (l == 59) {
                        __half2 hh = *reinterpret_cast<__half2*>(&w);
                        float2 hf = __half22float2(hh);
                        int row = m * 16 + l4 + 8 * q;
                        *(float2*)&s.h2[0][row * 192 + cg * 16 + 8 * j + 2 * l2i] = hf;
                    }
                }
            ((uint4*)fwN)[(cg * 2 + m) * 32 + lane] = make_uint4(wds[0], wds[1], wds[2], wds[3]);
        }
        if (l < 59) {
            gemm_pro(w2src, s.bias, cg, lane, acc, wv);
            asm volatile("cp.async.wait_group 0;" ::: "memory");
        }
        __syncthreads();
        buf ^= 1;
    }

    // ---- tail: level 58 reduce, level 59 lat + reduce, out_sfc ----
    lat_reduce(s, s.latp[1], 58, bbase, tid, out_lat, out_lev);   // latp[59&1]
    lat_mma(s.frag[buf], s.latp[0], warp, lane);
    __syncthreads();
    lat_reduce(s, s.latp[0], 59, bbase, tid, out_lat, out_lev);
    if (tid < 160) {
        int r = tid / 5, n = tid % 5;
        float sum = s.bsfco[n];
#pragma unroll 8
        for (int k = 0; k < 192; k++) sum += s.h2[0][r * 192 + k] * s.Wsfco[n * 193 + k];
        out_sfc[(bbase + r) * 5 + n] = sum * s.ysca[n];
    }
}

extern "C" void kernel_launch(void* const* d_in, const int* in_sizes, int n_in,
                              void* d_out, int out_size) {
    (void)in_sizes; (void)n_in; (void)out_size;
    const float* x_lev     = (const float*)d_in[0];
    const float* x_sfc     = (const float*)d_in[1];
    const float* h_mem     = (const float*)d_in[2];
    const float* xmean_lev = (const float*)d_in[3];
    const float* xdiv_lev  = (const float*)d_in[4];
    const float* xmean_sca = (const float*)d_in[5];
    const float* xdiv_sca  = (const float*)d_in[6];
    const float* yscale_lev = (const float*)d_in[7];
    const float* yscale_sca = (const float*)d_in[8];
    const float* Wih1 = (const float*)d_in[9];
    const float* Whh1 = (const float*)d_in[10];
    const float* b1   = (const float*)d_in[11];
    const float* Wih2 = (const float*)d_in[12];
    const float* Whh2 = (const float*)d_in[13];
    const float* b2   = (const float*)d_in[14];
    const float* Wsfc1 = (const float*)d_in[15];
    const float* bsfc1 = (const float*)d_in[16];
    const float* Wsfc2 = (const float*)d_in[17];
    const float* bsfc2 = (const float*)d_in[18];
    const float* Wtoa1 = (const float*)d_in[19];
    const float* btoa1 = (const float*)d_in[20];
    const float* Wtoa2 = (const float*)d_in[21];
    const float* btoa2 = (const float*)d_in[22];
    const float* Wlat  = (const float*)d_in[23];
    const float* blat  = (const float*)d_in[24];
    const float* Wout  = (const float*)d_in[25];
    const float* bout  = (const float*)d_in[26];
    const float* Wsfcout = (const float*)d_in[27];
    const float* bsfcout = (const float*)d_in[28];

    cudaFuncSetAttribute(lstm_main, cudaFuncAttributeMaxDynamicSharedMemorySize,
                         (int)sizeof(Smem));

    int npack = 12 * KT2 * 4 * 32 + 12 * KT1 * 4 * 32 + 12 * 2 * 32;
    pack_kernel<<<(npack + 255) / 256, 256>>>(Wih1, Whh1, Wih2, Whh2, Wlat);

    lstm_main<<<128, NTHR, sizeof(Smem)>>>(
        x_lev, x_sfc, h_mem, xmean_lev, xdiv_lev, xmean_sca, xdiv_sca,
        yscale_lev, yscale_sca, b1, b2,
        Wsfc1, bsfc1, Wsfc2, bsfc2, Wtoa1, btoa1, Wtoa2, btoa2,
        blat, Wout, bout, Wsfcout, bsfcout,
        (float*)d_out);
}

// round 17
// speedup vs baseline: 1.0677x; 1.0677x over previous
#include <cuda_runtime.h>
#include <cuda_fp16.h>
#include <cstdint>
#include <cstddef>

#define RB    32
#define NTHR  384
#define KT1   14
#define KT2   24
#define XL    6      // levels per xpack block

__device__ uint4 d_W1p[12 * KT1 * 4 * 32];
__device__ uint4 d_W2p[12 * KT2 * 4 * 32];
__device__ uint4 d_WlatP[12 * 2 * 32];
__device__ uint4 d_hs1f[128 * 60 * 768];
__device__ uint4 d_xf[128 * 60 * 128];      // x+hmem frags (kt12..13), 15.7MB

struct Smem {
    uint4 frag[2][KT2 * 2 * 32];
    float h2[2][RB * 192];
    float latp[2][12 * 128];
    float sn[RB * 24];
    float bias[768];            // i/f/o pre-scaled by 0.5
    float blat[16];
    float Wout[80];
    float bout[5];
    float Wsfco[5 * 193];
    float bsfco[5];
    float ysca[5];
    float yslev[300];
};

__device__ __forceinline__ float tanhf_fast(float x) {
    float y; asm("tanh.approx.f32 %0, %1;" : "=f"(y) : "f"(x)); return y;
}
__device__ __forceinline__ __half2 tanh_h2(__half2 x) {
    __half2 y;
    asm("tanh.approx.f16x2 %0, %1;" : "=r"(*(uint32_t*)&y) : "r"(*(uint32_t*)&x));
    return y;
}
__device__ __forceinline__ uint32_t h2pack(float x, float y) {
    __half2 h = __floats2half2_rn(x, y);
    return *reinterpret_cast<uint32_t*>(&h);
}

__device__ __forceinline__ void put_frag(uint32_t* fw, int row, int p, float v0, float v1) {
    int kt = p >> 3, qq = p & 7, mt = row >> 4, rr = row & 15;
    int cell = (kt * 2 + mt) * 32 + (rr & 7) * 4 + (qq & 3);
    int reg  = (qq >> 2) * 2 + (rr >> 3);
    fw[cell * 4 + reg] = h2pack(v0, v1);
}

__device__ __forceinline__ void mma4(float* c, const uint32_t* a, uint32_t b0, uint32_t b1) {
    asm volatile(
        "mma.sync.aligned.m16n8k16.row.col.f32.f16.f16.f32 "
        "{%0,%1,%2,%3},{%4,%5,%6,%7},{%8,%9},{%0,%1,%2,%3};\n"
        : "+f"(c[0]), "+f"(c[1]), "+f"(c[2]), "+f"(c[3])
        : "r"(a[0]), "r"(a[1]), "r"(a[2]), "r"(a[3]), "r"(b0), "r"(b1));
}

__device__ __forceinline__ void cpa16(uint32_t dst, const void* src) {
    asm volatile("cp.async.cg.shared.global [%0], [%1], 16;" :: "r"(dst), "l"(src) : "memory");
}

__device__ __forceinline__ void gemm_pro(
    const uint4* __restrict__ wsrc, const float* __restrict__ sbias,
    int cg, int lane, float acc[2][8][4], uint4 (&wv)[3][4])
{
    int l2i = lane & 3;
#pragma unroll
    for (int nt = 0; nt < 8; nt++) {
        float b0 = sbias[(nt >> 1) * 192 + cg * 16 + (nt & 1) * 8 + 2 * l2i];
        float b1 = sbias[(nt >> 1) * 192 + cg * 16 + (nt & 1) * 8 + 2 * l2i + 1];
        acc[0][nt][0] = b0; acc[0][nt][1] = b1; acc[0][nt][2] = b0; acc[0][nt][3] = b1;
        acc[1][nt][0] = b0; acc[1][nt][1] = b1; acc[1][nt][2] = b0; acc[1][nt][3] = b1;
    }
    const uint4* wp = wsrc + lane;
#pragma unroll
    for (int np = 0; np < 4; np++) wv[0][np] = __ldg(&wp[np * 32]);
#pragma unroll
    for (int np = 0; np < 4; np++) wv[1][np] = __ldg(&wp[(4 + np) * 32]);
}

template<int KT>
__device__ __forceinline__ void gemm_main(
    const uint4* __restrict__ fr, const uint4* __restrict__ wsrc,
    int lane, float acc[2][8][4], uint4 (&wv)[3][4])
{
    const uint4* wp = wsrc + lane;
    const uint4* fb = fr + lane;
    uint4 f[2][2];
    f[0][0] = fb[0]; f[0][1] = fb[32];
#pragma unroll
    for (int kt = 0; kt < KT; kt++) {
        const int cur = kt % 3;
        if (kt + 2 < KT) {
            const uint4* wpn = wp + (kt + 2) * 4 * 32;
            const int nb = (kt + 2) % 3;
#pragma unroll
            for (int np = 0; np < 4; np++) wv[nb][np] = __ldg(&wpn[np * 32]);
        }
        if (kt + 1 < KT) {
            f[(kt + 1) & 1][0] = fb[(kt + 1) * 64];
            f[(kt + 1) & 1][1] = fb[(kt + 1) * 64 + 32];
        }
        const uint32_t* a0 = (const uint32_t*)&f[kt & 1][0];
        const uint32_t* a1 = (const uint32_t*)&f[kt & 1][1];
#pragma unroll
        for (int np = 0; np < 4; np++) {
            mma4(acc[0][2 * np],     a0, wv[cur][np].x, wv[cur][np].y);
            mma4(acc[1][2 * np],     a1, wv[cur][np].x, wv[cur][np].y);
            mma4(acc[0][2 * np + 1], a0, wv[cur][np].z, wv[cur][np].w);
            mma4(acc[1][2 * np + 1], a1, wv[cur][np].z, wv[cur][np].w);
        }
    }
#pragma unroll
    for (int np = 0; np < 8; np++)
        asm volatile("prefetch.global.L1 [%0];" :: "l"((const void*)(wp + np * 32)));
}

// gates i/f/g fp32 (precision-critical); output stage f16x2
__device__ __forceinline__ uint32_t ew_pair(const float acc[8][4], float* cr,
                                            int j, int q) {
    float gi0 = acc[0+j][2*q], gi1 = acc[0+j][2*q+1];
    float gf0 = acc[2+j][2*q], gf1 = acc[2+j][2*q+1];
    float gg0 = acc[4+j][2*q], gg1 = acc[4+j][2*q+1];
    float go0 = acc[6+j][2*q], go1 = acc[6+j][2*q+1];
    float si0 = fmaf(tanhf_fast(gi0), 0.5f, 0.5f);
    float si1 = fmaf(tanhf_fast(gi1), 0.5f, 0.5f);
    float sf0 = fmaf(tanhf_fast(gf0), 0.5f, 0.5f);
    float sf1 = fmaf(tanhf_fast(gf1), 0.5f, 0.5f);
    float c0 = sf0 * cr[0] + si0 * tanhf_fast(gg0);
    float c1 = sf1 * cr[1] + si1 * tanhf_fast(gg1);
    cr[0] = c0; cr[1] = c1;
    const __half2 hh = __floats2half2_rn(0.5f, 0.5f);
    __half2 so = __hfma2(tanh_h2(__floats2half2_rn(go0, go1)), hh, hh);
    __half2 h = __hmul2(so, tanh_h2(__floats2half2_rn(c0, c1)));
    return *reinterpret_cast<uint32_t*>(&h);
}

__device__ __forceinline__ void lat_mma(const uint4* __restrict__ fr, float* __restrict__ latp,
                                        int w, int lane) {
    int mt = w / 6, rem = w % 6, ntL = rem / 3, ktr = rem % 3;
    float acc[4] = {0.f, 0.f, 0.f, 0.f};
    const uint4* fb = fr + mt * 32 + lane;
#pragma unroll
    for (int i = 0; i < 4; i++) {
        int kt = ktr * 4 + i;
        uint4 f = fb[kt * 64];
        uint4 u = __ldg(&d_WlatP[(kt * 2 + ntL) * 32 + lane]);
        mma4(acc, (const uint32_t*)&f, u.x, u.y);
        mma4(acc, (const uint32_t*)&f, u.z, u.w);
    }
    float* base = latp + w * 128;
    int r0 = lane >> 2, c0 = (lane & 3) * 2;
    *(float2*)&base[r0 * 8 + c0]       = make_float2(acc[0], acc[1]);
    *(float2*)&base[(r0 + 8) * 8 + c0] = make_float2(acc[2], acc[3]);
}

__device__ __forceinline__ void lat_reduce(Smem& s, const float* __restrict__ lp,
    int lm, int bbase, int tid, float* __restrict__ out_lat, float* __restrict__ out_lev)
{
#pragma unroll 1
    for (int it = 0; it < 2; it++) {
        int idx = it * NTHR + tid;
        if (idx < 512) {
            int r = idx >> 4, j16 = idx & 15;
            int mt = r >> 4, rr = r & 15, ntL = j16 >> 3, cc = j16 & 7;
            int tb = mt * 6 + ntL * 3;
            float sum = s.blat[j16]
                      + lp[(tb + 0) * 128 + rr * 8 + cc]
                      + lp[(tb + 1) * 128 + rr * 8 + cc]
                      + lp[(tb + 2) * 128 + rr * 8 + cc];
            out_lat[((size_t)(bbase + r) * 60 + lm) * 16 + j16] = sum;
            float v0 = sum * s.Wout[0 * 16 + j16];
            float v1 = sum * s.Wout[1 * 16 + j16];
            float v2 = sum * s.Wout[2 * 16 + j16];
            float v3 = sum * s.Wout[3 * 16 + j16];
            float v4 = sum * s.Wout[4 * 16 + j16];
#pragma unroll
            for (int off = 8; off >= 1; off >>= 1) {
                v0 += __shfl_xor_sync(0xffffffffu, v0, off, 16);
                v1 += __shfl_xor_sync(0xffffffffu, v1, off, 16);
                v2 += __shfl_xor_sync(0xffffffffu, v2, off, 16);
                v3 += __shfl_xor_sync(0xffffffffu, v3, off, 16);
                v4 += __shfl_xor_sync(0xffffffffu, v4, off, 16);
            }
            if (j16 == 0) {
                size_t ob = ((size_t)(bbase + r) * 60 + lm) * 5;
                out_lev[ob + 0] = (v0 + s.bout[0]) * s.yslev[lm * 5 + 0];
                out_lev[ob + 1] = (v1 + s.bout[1]) * s.yslev[lm * 5 + 1];
                out_lev[ob + 2] = (v2 + s.bout[2]) * s.yslev[lm * 5 + 2];
                out_lev[ob + 3] = (v3 + s.bout[3]) * s.yslev[lm * 5 + 3];
                out_lev[ob + 4] = (v4 + s.bout[4]) * s.yslev[lm * 5 + 4];
            }
        }
    }
}

// precompute x+hmem fragments for all levels (smem-staged, coalesced)
__global__ void xpack_kernel(const float* __restrict__ x_lev, const float* __restrict__ h_mem,
                             const float* __restrict__ xmean_lev, const float* __restrict__ xdiv_lev) {
    __shared__ float sx[32 * XL * 15];
    __shared__ float sh[32 * XL * 16];
    int blk = blockIdx.x / 10, lg = blockIdx.x % 10;
    int l0 = lg * XL;
    int tid = threadIdx.x;
    for (int i = tid; i < 32 * XL * 15; i += 256) {
        int row = i / (XL * 15), rem = i % (XL * 15);
        sx[i] = x_lev[((size_t)(blk * 32 + row) * 60 + l0) * 15 + rem];
    }
    for (int i = tid; i < 32 * XL * 16; i += 256) {
        int row = i / (XL * 16), rem = i % (XL * 16);
        sh[i] = h_mem[((size_t)(blk * 32 + row) * 60 + l0) * 16 + rem];
    }
    __syncthreads();
    for (int t = tid; t < XL * 128; t += 256) {
        int lev = t >> 7, cellloc = t & 127;
        int ln = l0 + lev;
        int ktl = cellloc >> 6, mt = (cellloc >> 5) & 1, lane = cellloc & 31;
        uint32_t w[4];
#pragma unroll
        for (int reg = 0; reg < 4; reg++) {
            int rr = (lane >> 2) + 8 * (reg & 1);
            int qq = (lane & 3) + 4 * (reg >> 1);
            int row = mt * 16 + rr;
            int pp = ktl * 8 + qq;
            float v[2];
#pragma unroll
            for (int u = 0; u < 2; u++) {
                int j = pp * 2 + u;
                if (j < 15)
                    v[u] = (sx[row * (XL * 15) + lev * 15 + j] - xmean_lev[ln * 15 + j])
                           / xdiv_lev[ln * 15 + j];
                else if (j < 31)
                    v[u] = sh[row * (XL * 16) + lev * 16 + (j - 15)];
                else
                    v[u] = 0.0f;
            }
            w[reg] = h2pack(v[0], v[1]);
        }
        d_xf[((size_t)(blk * 60 + ln) << 7) + cellloc] = make_uint4(w[0], w[1], w[2], w[3]);
    }
}

__global__ void pack_kernel(const float* __restrict__ Wih1, const float* __restrict__ Whh1,
                            const float* __restrict__ Wih2, const float* __restrict__ Whh2,
                            const float* __restrict__ Wlat) {
    int tid = blockIdx.x * blockDim.x + threadIdx.x;
    const int N2 = 12 * KT2 * 4 * 32, N1 = 12 * KT1 * 4 * 32, NL = 12 * 2 * 32;
    if (tid < N2) {
        int lane = tid & 31, t = tid >> 5;
        int np = t % 4, kt = (t / 4) % KT2, cg = t / (4 * KT2);
        int k0 = kt * 16 + (lane & 3) * 2;
        int ks[4] = {k0, k0 + 1, k0 + 8, k0 + 9};
        uint32_t word[2][2];
#pragma unroll
        for (int sub = 0; sub < 2; sub++) {
            int c = (np * 2 + sub) * 8 + (lane >> 2);
            int gate = c >> 4;
            float sc = (gate == 2) ? 1.0f : 0.5f;
            int n = gate * 192 + cg * 16 + (c & 15);
            float v[4];
#pragma unroll
            for (int i = 0; i < 4; i++) {
                int k = ks[i];
                v[i] = sc * ((k < 192) ? Whh2[n * 192 + k] : Wih2[n * 192 + (k - 192)]);
            }
            word[sub][0] = h2pack(v[0], v[1]); word[sub][1] = h2pack(v[2], v[3]);
        }
        d_W2p[tid] = make_uint4(word[0][0], word[0][1], word[1][0], word[1][1]);
    } else if (tid < N2 + N1) {
        int t0 = tid - N2;
        int lane = t0 & 31, t = t0 >> 5;
        int np = t % 4, kt = (t / 4) % KT1, cg = t / (4 * KT1);
        int k0 = kt * 16 + (lane & 3) * 2;
        int ks[4] = {k0, k0 + 1, k0 + 8, k0 + 9};
        uint32_t word[2][2];
#pragma unroll
        for (int sub = 0; sub < 2; sub++) {
            int c = (np * 2 + sub) * 8 + (lane >> 2);
            int gate = c >> 4;
            float sc = (gate == 2) ? 1.0f : 0.5f;
            int n = gate * 192 + cg * 16 + (c & 15);
            float v[4];
#pragma unroll
            for (int i = 0; i < 4; i++) {
                int k = ks[i];
                float w;
                if (k < 192)      w = Whh1[n * 192 + k];
                else if (k < 223) w = Wih1[n * 31 + (k - 192)];
                else              w = 0.0f;
                v[i] = sc * w;
            }
            word[sub][0] = h2pack(v[0], v[1]); word[sub][1] = h2pack(v[2], v[3]);
        }
        d_W1p[t0] = make_uint4(word[0][0], word[0][1], word[1][0], word[1][1]);
    } else if (tid < N2 + N1 + NL) {
        int t0 = tid - N2 - N1;
        int lane = t0 & 31, t = t0 >> 5;
        int nt = t % 2, kt = t / 2;
        int n = nt * 8 + (lane >> 2);
        int k0 = kt * 16 + (lane & 3) * 2;
        int ks[4] = {k0, k0 + 1, k0 + 8, k0 + 9};
        float hi[4], lo[4];
#pragma unroll
        for (int i = 0; i < 4; i++) {
            float w = Wlat[n * 192 + ks[i]];
            __half h = __float2half(w);
            hi[i] = __half2float(h);
            lo[i] = w - hi[i];
        }
        d_WlatP[t0] = make_uint4(h2pack(hi[0], hi[1]), h2pack(hi[2], hi[3]),
                                 h2pack(lo[0], lo[1]), h2pack(lo[2], lo[3]));
    }
}

__global__ void __launch_bounds__(NTHR, 1) lstm_main(
    const float* __restrict__ x_sfc,
    const float* __restrict__ xmean_sca, const float* __restrict__ xdiv_sca,
    const float* __restrict__ yscale_lev, const float* __restrict__ yscale_sca,
    const float* __restrict__ b1, const float* __restrict__ b2,
    const float* __restrict__ Wsfc1, const float* __restrict__ bsfc1,
    const float* __restrict__ Wsfc2, const float* __restrict__ bsfc2,
    const float* __restrict__ Wtoa1, const float* __restrict__ btoa1,
    const float* __restrict__ Wtoa2, const float* __restrict__ btoa2,
    const float* __restrict__ blat, const float* __restrict__ Wout,
    const float* __restrict__ bout,
    const float* __restrict__ Wsfcout, const float* __restrict__ bsfcout,
    float* __restrict__ out)
{
    extern __shared__ char smraw[];
    Smem& s = *reinterpret_cast<Smem*>(smraw);
    const int tid = threadIdx.x, warp = tid >> 5, lane = tid & 31;
    const int cg = warp;
    const int l2i = lane & 3, l4 = lane >> 2;
    const int bbase = blockIdx.x * RB;
    float* out_lev = out;
    float* out_sfc = out + 4096 * 60 * 5;
    float* out_lat = out_sfc + 4096 * 5;

    for (int i = tid; i < RB * 24; i += NTHR) {
        int r = i / 24, k = i % 24;
        s.sn[i] = (x_sfc[(bbase + r) * 24 + k] - xmean_sca[k]) / xdiv_sca[k];
    }
    for (int i = tid; i < 768; i += NTHR)
        s.bias[i] = ((i / 192) == 2) ? b1[i] : 0.5f * b1[i];
    for (int i = tid; i < 16; i += NTHR) s.blat[i] = blat[i];
    for (int i = tid; i < 80; i += NTHR) s.Wout[i] = Wout[i];
    for (int i = tid; i < 5; i += NTHR) {
        s.bout[i] = bout[i]; s.bsfco[i] = bsfcout[i];
        s.ysca[i] = __frcp_rn(yscale_sca[i]);
    }
    for (int i = tid; i < 5 * 192; i += NTHR) { int n = i / 192, k = i % 192; s.Wsfco[n * 193 + k] = Wsfcout[i]; }
    for (int i = tid; i < 300; i += NTHR) s.yslev[i] = __frcp_rn(yscale_lev[i]);
    __syncthreads();

#pragma unroll 1
    for (int it = 0; it < 16; it++) {
        int idx = it * NTHR + tid, r = idx / 192, k = idx % 192;
        float s1 = bsfc1[k], s2 = bsfc2[k];
#pragma unroll 4
        for (int t = 0; t < 24; t++) {
            float v = s.sn[r * 24 + t];
            s1 += v * Wsfc1[k * 24 + t];
            s2 += v * Wsfc2[k * 24 + t];
        }
        s.h2[0][r * 192 + k] = tanhf_fast(s1);
        s.h2[1][r * 192 + k] = tanhf_fast(s2);
    }
    __syncthreads();

    float creg[2][2][2][2];
#pragma unroll
    for (int m = 0; m < 2; m++)
#pragma unroll
        for (int j = 0; j < 2; j++)
#pragma unroll
            for (int q = 0; q < 2; q++)
#pragma unroll
                for (int e = 0; e < 2; e++)
                    creg[m][j][q][e] = s.h2[1][(m * 16 + l4 + 8 * q) * 192 + cg * 16 + 8 * j + 2 * l2i + e];

    int buf = 0;
    for (int it = 0; it < 8; it++) {
        int idx = it * NTHR + tid, r = idx / 96, cp = idx % 96;
        put_frag((uint32_t*)s.frag[0], r, cp, s.h2[0][r * 192 + 2 * cp], s.h2[0][r * 192 + 2 * cp + 1]);
    }
    if (tid < 128)  // x frags for level 59
        s.frag[0][768 + tid] = d_xf[((size_t)(blockIdx.x * 60 + 59) << 7) + tid];

    const uint4* w1src = d_W1p + cg * (KT1 * 4 * 32);
    const uint4* w2src = d_W2p + cg * (KT2 * 4 * 32);
    float acc[2][8][4];
    uint4 wv[3][4];

    gemm_pro(w1src, s.bias, cg, lane, acc, wv);
    __syncthreads();

    // ---- layer 1 ----
    for (int l = 59; l >= 0; l--) {
        if (l > 0) {   // earliest fetch of next level's x frags
            if (tid < 128) {
                uint32_t ds = (uint32_t)__cvta_generic_to_shared(s.frag[buf ^ 1] + 768 + tid);
                cpa16(ds, d_xf + ((size_t)(blockIdx.x * 60 + (l - 1)) << 7) + tid);
            }
            asm volatile("cp.async.commit_group;" ::: "memory");
        }
        gemm_main<KT1>(s.frag[buf], w1src, lane, acc, wv);
        uint32_t* fwN = (uint32_t*)s.frag[buf ^ 1];
#pragma unroll
        for (int m = 0; m < 2; m++) {
            uint32_t wds[4];
#pragma unroll
            for (int j = 0; j < 2; j++)
#pragma unroll
                for (int q = 0; q < 2; q++)
                    wds[2 * j + q] = ew_pair(acc[m], creg[m][j][q], j, q);
            uint4 w4 = make_uint4(wds[0], wds[1], wds[2], wds[3]);
            ((uint4*)fwN)[(cg * 2 + m) * 32 + lane] = w4;
            d_hs1f[(size_t)(blockIdx.x * 60 + l) * 768 + (cg * 2 + m) * 32 + lane] = w4;
        }
        if (l > 0) {
            gemm_pro(w1src, s.bias, cg, lane, acc, wv);
            asm volatile("cp.async.wait_group 0;" ::: "memory");
        }
        __syncthreads();
        buf ^= 1;
    }

    // ---- transition ----  (buf == 0)
    for (int i = tid; i < 768; i += NTHR)
        s.bias[i] = ((i / 192) == 2) ? b2[i] : 0.5f * b2[i];
#pragma unroll 1
    for (int it = 0; it < 16; it++) {
        int idx = it * NTHR + tid, r = idx / 192, k = idx % 192;
        float t0 = s.sn[r * 24 + 0], t1 = s.sn[r * 24 + 1];
        s.h2[0][r * 192 + k] = tanhf_fast(btoa1[k] + t0 * Wtoa1[k * 2] + t1 * Wtoa1[k * 2 + 1]);
        s.h2[1][r * 192 + k] = tanhf_fast(btoa2[k] + t0 * Wtoa2[k * 2] + t1 * Wtoa2[k * 2 + 1]);
    }
    __syncthreads();
#pragma unroll
    for (int m = 0; m < 2; m++)
#pragma unroll
        for (int j = 0; j < 2; j++)
#pragma unroll
            for (int q = 0; q < 2; q++)
#pragma unroll
                for (int e = 0; e < 2; e++)
                    creg[m][j][q][e] = s.h2[1][(m * 16 + l4 + 8 * q) * 192 + cg * 16 + 8 * j + 2 * l2i + e];
    for (int it = 0; it < 8; it++) {
        int idx = it * NTHR + tid, r = idx / 96, cp = idx % 96;
        put_frag((uint32_t*)s.frag[buf], r, cp, s.h2[0][r * 192 + 2 * cp], s.h2[0][r * 192 + 2 * cp + 1]);
    }
    {
        const uint4* src = d_hs1f + (size_t)(blockIdx.x * 60 + 0) * 768;
        uint4* dst = s.frag[buf] + 768;
        dst[tid] = src[tid];
        dst[NTHR + tid] = src[NTHR + tid];
    }
    gemm_pro(w2src, s.bias, cg, lane, acc, wv);
    __syncthreads();

    // ---- layer 2 (R15 schedule) ----
    for (int l = 0; l < 60; l++) {
        gemm_main<KT2>(s.frag[buf], w2src, lane, acc, wv);
        uint32_t* fwN = (uint32_t*)s.frag[buf ^ 1];
        if (l > 0) lat_mma(s.frag[buf], s.latp[l & 1], warp, lane);
        if (l < 59) {
            const uint4* src = d_hs1f + (size_t)(blockIdx.x * 60 + (l + 1)) * 768;
            uint32_t ds = (uint32_t)__cvta_generic_to_shared(s.frag[buf ^ 1] + 768 + tid);
            cpa16(ds, src + tid);
            cpa16(ds + NTHR * 16, src + NTHR + tid);
            asm volatile("cp.async.commit_group;" ::: "memory");
        }
#pragma unroll
        for (int m = 0; m < 2; m++) {
            uint32_t wds[4];
#pragma unroll
            for (int j = 0; j < 2; j++)
#pragma unroll
                for (int q = 0; q < 2; q++) {
                    uint32_t w = ew_pair(acc[m], creg[m][j][q], j, q);
                    wds[2 * j + q] = w;
                    if (l == 59) {
                        __half2 hh = *reinterpret_cast<__half2*>(&w);
                        float2 hf = __half22float2(hh);
                        int row = m * 16 + l4 + 8 * q;
                        *(float2*)&s.h2[0][row * 192 + cg * 16 + 8 * j + 2 * l2i] = hf;
                    }
                }
            ((uint4*)fwN)[(cg * 2 + m) * 32 + lane] = make_uint4(wds[0], wds[1], wds[2], wds[3]);
        }
        if (l < 59) {
            gemm_pro(w2src, s.bias, cg, lane, acc, wv);
            asm volatile("cp.async.wait_group 0;" ::: "memory");
        }
        __syncthreads();
        buf ^= 1;
        if (l > 0) lat_reduce(s, s.latp[l & 1], l - 1, bbase, tid, out_lat, out_lev);
    }

    // ---- tail: level 59 lat + reduce, out_sfc ----
    lat_mma(s.frag[buf], s.latp[0], warp, lane);
    __syncthreads();
    lat_reduce(s, s.latp[0], 59, bbase, tid, out_lat, out_lev);
    if (tid < 160) {
        int r = tid / 5, n = tid % 5;
        float sum = s.bsfco[n];
#pragma unroll 8
        for (int k = 0; k < 192; k++) sum += s.h2[0][r * 192 + k] * s.Wsfco[n * 193 + k];
        out_sfc[(bbase + r) * 5 + n] = sum * s.ysca[n];
    }
}

extern "C" void kernel_launch(void* const* d_in, const int* in_sizes, int n_in,
                              void* d_out, int out_size) {
    (void)in_sizes; (void)n_in; (void)out_size;
    const float* x_lev     = (const float*)d_in[0];
    const float* x_sfc     = (const float*)d_in[1];
    const float* h_mem     = (const float*)d_in[2];
    const float* xmean_lev = (const float*)d_in[3];
    const float* xdiv_lev  = (const float*)d_in[4];
    const float* xmean_sca = (const float*)d_in[5];
    const float* xdiv_sca  = (const float*)d_in[6];
    const float* yscale_lev = (const float*)d_in[7];
    const float* yscale_sca = (const float*)d_in[8];
    const float* Wih1 = (const float*)d_in[9];
    const float* Whh1 = (const float*)d_in[10];
    const float* b1   = (const float*)d_in[11];
    const float* Wih2 = (const float*)d_in[12];
    const float* Whh2 = (const float*)d_in[13];
    const float* b2   = (const float*)d_in[14];
    const float* Wsfc1 = (const float*)d_in[15];
    const float* bsfc1 = (const float*)d_in[16];
    const float* Wsfc2 = (const float*)d_in[17];
    const float* bsfc2 = (const float*)d_in[18];
    const float* Wtoa1 = (const float*)d_in[19];
    const float* btoa1 = (const float*)d_in[20];
    const float* Wtoa2 = (const float*)d_in[21];
    const float* btoa2 = (const float*)d_in[22];
    const float* Wlat  = (const float*)d_in[23];
    const float* blat  = (const float*)d_in[24];
    const float* Wout  = (const float*)d_in[25];
    const float* bout  = (const float*)d_in[26];
    const float* Wsfcout = (const float*)d_in[27];
    const float* bsfcout = (const float*)d_in[28];

    cudaFuncSetAttribute(lstm_main, cudaFuncAttributeMaxDynamicSharedMemorySize,
                         (int)sizeof(Smem));

    int npack = 12 * KT2 * 4 * 32 + 12 * KT1 * 4 * 32 + 12 * 2 * 32;
    pack_kernel<<<(npack + 255) / 256, 256>>>(Wih1, Whh1, Wih2, Whh2, Wlat);
    xpack_kernel<<<128 * 10, 256>>>(x_lev, h_mem, xmean_lev, xdiv_lev);

    lstm_main<<<128, NTHR, sizeof(Smem)>>>(
        x_sfc, xmean_sca, xdiv_sca,
        yscale_lev, yscale_sca, b1, b2,
        Wsfc1, bsfc1, Wsfc2, bsfc2, Wtoa1, btoa1, Wtoa2, btoa2,
        blat, Wout, bout, Wsfcout, bsfcout,
        (float*)d_out);
}